// round 4
// baseline (speedup 1.0000x reference)
#include <cuda_runtime.h>

#define HW      49
#define QP      50              // q padded to even
#define PP      56              // p padded to 8 warps x 7 rows (zero-filled)
#define ROWF    (2*QP)          // duplicated A row: 100 floats = 400 B (16B mult)
#define CCOLS   512
#define CT      128             // c-tile per CTA
#define THREADS 256

typedef unsigned long long u64;

// Packed fp32x2 FMA (Blackwell FFMA2) — only reachable via PTX.
__device__ __forceinline__ u64 fma2(u64 a, u64 b, u64 c) {
    u64 d;
    asm("fma.rn.f32x2 %0, %1, %2, %3;" : "=l"(d) : "l"(a), "l"(b), "l"(c));
    return d;
}

__global__ __launch_bounds__(THREADS, 4)
void bmm_tr_residual_kernel(const float* __restrict__ x,
                            const float* __restrict__ attn,
                            const float* __restrict__ Dm,
                            const float* __restrict__ alpha,
                            float* __restrict__ out)
{
    // A duplicated per element; one LDS.128 broadcast = 2 q's of fma2 operands.
    __shared__ __align__(16) float sA2[PP * ROWF];   // 22400 B (rows 49..55 zero)
    __shared__ __align__(16) float sD[QP * CT];      // 25600 B; reused as Y[c][p]

    const int n   = blockIdx.y;
    const int c0  = blockIdx.x * CT;
    const int tid = threadIdx.x;

    // ---- stage attn[n] duplicated; pad p to 56 and q to 50 with zeros ----
    const float* An = attn + (size_t)n * HW * HW;
    for (int i = tid; i < PP * QP; i += THREADS) {
        int p = i / QP, q = i % QP;
        float v = (p < HW && q < HW) ? An[p * HW + q] : 0.0f;
        sA2[p * ROWF + 2 * q]     = v;
        sA2[p * ROWF + 2 * q + 1] = v;
    }

    // ---- stage D[n][:, c0:c0+CT], q padded with zeros, float4 coalesced ----
    const float* Dn = Dm + (size_t)n * HW * CCOLS + c0;
    float4* sD4 = (float4*)sD;
    for (int i = tid; i < QP * (CT / 4); i += THREADS) {
        int q = i / (CT / 4);
        int j = i % (CT / 4);
        sD4[i] = (q < HW) ? *(const float4*)(Dn + (size_t)q * CCOLS + j * 4)
                          : make_float4(0.f, 0.f, 0.f, 0.f);
    }
    __syncthreads();

    // ---- compute: thread owns c {4tc..4tc+3}, p rows {tp+8k}, k=0..6 ----
    const int tc = tid & 31;
    const int tp = tid >> 5;

    u64 acc[7][2];
#pragma unroll
    for (int k = 0; k < 7; ++k) { acc[k][0] = 0ull; acc[k][1] = 0ull; }

    const char* sAbase = (const char*)sA2 + tp * (ROWF * 4);
    const char* sBbase = (const char*)sD + 16 * tc;

    for (int qb = 0; qb < QP / 2; ++qb) {          // 25 blocks of 2 q's
        // B: one LDS.128 per q -> two u64 c-pairs each, no packing MOVs.
        ulonglong2 B0 = *(const ulonglong2*)(sBbase + (2 * qb)     * (CT * 4));
        ulonglong2 B1 = *(const ulonglong2*)(sBbase + (2 * qb + 1) * (CT * 4));
#pragma unroll
        for (int k = 0; k < 7; ++k) {
            // A: one LDS.128 broadcast = {(a_q0,a_q0),(a_q1,a_q1)}.
            ulonglong2 A2 = *(const ulonglong2*)(sAbase + k * (8 * ROWF * 4) + 16 * qb);
            acc[k][0] = fma2(A2.x, B0.x, acc[k][0]);
            acc[k][1] = fma2(A2.x, B0.y, acc[k][1]);
            acc[k][0] = fma2(A2.y, B1.x, acc[k][0]);
            acc[k][1] = fma2(A2.y, B1.y, acc[k][1]);
        }
    }
    __syncthreads();   // all reads of sD done — safe to reuse as Y

    // ---- scatter Y into smem as [c][p] so gmem writes are contiguous ----
#pragma unroll
    for (int k = 0; k < 7; ++k) {
        int p = tp + 8 * k;
        if (p < HW) {
#pragma unroll
            for (int w = 0; w < 2; ++w) {
                int c = 4 * tc + 2 * w;
                float lo, hi;
                asm("mov.b64 {%0,%1}, %2;" : "=f"(lo), "=f"(hi) : "l"(acc[k][w]));
                sD[c * HW + p]       = lo;
                sD[(c + 1) * HW + p] = hi;
            }
        }
    }
    __syncthreads();

    // ---- residual epilogue: out[n, c0:c0+CT, :] is contiguous CT*HW floats ----
    const float  al   = alpha[0];
    const size_t base = (size_t)n * CCOLS * HW + (size_t)c0 * HW;
    const float4* x4  = (const float4*)(x + base);
    const float4* y4  = (const float4*)sD;
    float4*       o4  = (float4*)(out + base);

    for (int i = tid; i < (CT * HW) / 4; i += THREADS) {
        float4 xv = x4[i];
        float4 yv = y4[i];
        float4 ov;
        ov.x = fmaf(al, yv.x, xv.x);
        ov.y = fmaf(al, yv.y, xv.y);
        ov.z = fmaf(al, yv.z, xv.z);
        ov.w = fmaf(al, yv.w, xv.w);
        o4[i] = ov;
    }
}

extern "C" void kernel_launch(void* const* d_in, const int* in_sizes, int n_in,
                              void* d_out, int out_size)
{
    const float* x     = (const float*)d_in[0];
    const float* attn  = (const float*)d_in[1];
    const float* Dm    = (const float*)d_in[2];
    const float* alpha = (const float*)d_in[3];
    float*       out   = (float*)d_out;

    const int N = in_sizes[1] / (HW * HW);   // 2048
    dim3 grid(CCOLS / CT, N);                // (4, 2048)
    bmm_tr_residual_kernel<<<grid, THREADS>>>(x, attn, Dm, alpha, out);
}

// round 5
// speedup vs baseline: 1.0147x; 1.0147x over previous
#include <cuda_runtime.h>

#define HW      49
#define QP      50              // q padded to even
#define PP      56              // p padded to 8 warps x 7 rows (zero-filled)
#define ROWF    (2*QP)          // duplicated A row: 100 floats = 400 B
#define CCOLS   512
#define CT      128             // c-tile per CTA
#define THREADS 256

typedef unsigned long long u64;

// Packed fp32x2 FMA (Blackwell FFMA2) — only reachable via PTX.
__device__ __forceinline__ u64 fma2(u64 a, u64 b, u64 c) {
    u64 d;
    asm("fma.rn.f32x2 %0, %1, %2, %3;" : "=l"(d) : "l"(a), "l"(b), "l"(c));
    return d;
}

__global__ __launch_bounds__(THREADS, 4)
void bmm_tr_residual_kernel(const float* __restrict__ x,
                            const float* __restrict__ attn,
                            const float* __restrict__ Dm,
                            const float* __restrict__ alpha,
                            float* __restrict__ out)
{
    // A duplicated per element; one LDS.128 broadcast = 2 q's of fma2 operands.
    __shared__ __align__(16) float sA2[PP * ROWF];   // 22400 B (rows 49..55 zero)
    __shared__ __align__(16) float sD[QP * CT];      // 25600 B; reused as Y[c][p]

    const int n   = blockIdx.y;
    const int c0  = blockIdx.x * CT;
    const int tid = threadIdx.x;

    // ---- stage attn[n] duplicated; p padded to 56, q padded to 50, zeros ----
    const float* An = attn + (size_t)n * HW * HW;
    for (int i = tid; i < PP * QP; i += THREADS) {
        int p = i / QP, q = i % QP;
        float v = (p < HW && q < HW) ? An[p * HW + q] : 0.0f;
        sA2[p * ROWF + 2 * q]     = v;
        sA2[p * ROWF + 2 * q + 1] = v;
    }

    // ---- stage D[n][:, c0:c0+CT], q padded with zeros, float4 coalesced ----
    const float* Dn = Dm + (size_t)n * HW * CCOLS + c0;
    float4* sD4 = (float4*)sD;
    for (int i = tid; i < QP * (CT / 4); i += THREADS) {
        int q = i / (CT / 4);
        int j = i % (CT / 4);
        sD4[i] = (q < HW) ? *(const float4*)(Dn + (size_t)q * CCOLS + j * 4)
                          : make_float4(0.f, 0.f, 0.f, 0.f);
    }
    __syncthreads();

    // ---- compute: thread owns c {4tc..4tc+3}, p rows {tp+8k}, k=0..6 ----
    const int tc = tid & 31;
    const int tp = tid >> 5;

    u64 acc[7][2];
#pragma unroll
    for (int k = 0; k < 7; ++k) { acc[k][0] = 0ull; acc[k][1] = 0ull; }

    // Typed shared pointers; per-iter advance by constant stride so every
    // load is LDS.128 [base + imm]. (char* arithmetic in R4 bloated alu to 21%.)
    const float* pA = sA2 + tp * ROWF;   // +4 floats (16B, 2 dup'd q) per iter
    const float* pB = sD + 4 * tc;       // +2*CT floats (2 rows) per iter

#pragma unroll 5
    for (int qb = 0; qb < QP / 2; ++qb, pA += 4, pB += 2 * CT) {
        ulonglong2 B0 = *(const ulonglong2*)(pB);        // q0: c pairs (x,y)
        ulonglong2 B1 = *(const ulonglong2*)(pB + CT);   // q1
#pragma unroll
        for (int k = 0; k < 7; ++k) {
            // broadcast {(a_q0,a_q0),(a_q1,a_q1)} for p = tp+8k
            ulonglong2 A2 = *(const ulonglong2*)(pA + k * (8 * ROWF));
            acc[k][0] = fma2(A2.x, B0.x, acc[k][0]);
            acc[k][1] = fma2(A2.x, B0.y, acc[k][1]);
            acc[k][0] = fma2(A2.y, B1.x, acc[k][0]);
            acc[k][1] = fma2(A2.y, B1.y, acc[k][1]);
        }
    }
    __syncthreads();   // all reads of sD done — safe to reuse as Y

    // ---- scatter Y into smem as [c][p] so gmem writes are contiguous ----
#pragma unroll
    for (int k = 0; k < 7; ++k) {
        int p = tp + 8 * k;
        if (p < HW) {
#pragma unroll
            for (int w = 0; w < 2; ++w) {
                int c = 4 * tc + 2 * w;
                float lo, hi;
                asm("mov.b64 {%0,%1}, %2;" : "=f"(lo), "=f"(hi) : "l"(acc[k][w]));
                sD[c * HW + p]       = lo;
                sD[(c + 1) * HW + p] = hi;
            }
        }
    }
    __syncthreads();

    // ---- residual epilogue: out[n, c0:c0+CT, :] is contiguous CT*HW floats ----
    const float  al   = alpha[0];
    const size_t base = (size_t)n * CCOLS * HW + (size_t)c0 * HW;
    const float4* x4  = (const float4*)(x + base);
    const float4* y4  = (const float4*)sD;
    float4*       o4  = (float4*)(out + base);

    for (int i = tid; i < (CT * HW) / 4; i += THREADS) {
        float4 xv = x4[i];
        float4 yv = y4[i];
        float4 ov;
        ov.x = fmaf(al, yv.x, xv.x);
        ov.y = fmaf(al, yv.y, xv.y);
        ov.z = fmaf(al, yv.z, xv.z);
        ov.w = fmaf(al, yv.w, xv.w);
        o4[i] = ov;
    }
}

extern "C" void kernel_launch(void* const* d_in, const int* in_sizes, int n_in,
                              void* d_out, int out_size)
{
    const float* x     = (const float*)d_in[0];
    const float* attn  = (const float*)d_in[1];
    const float* Dm    = (const float*)d_in[2];
    const float* alpha = (const float*)d_in[3];
    float*       out   = (float*)d_out;

    const int N = in_sizes[1] / (HW * HW);   // 2048
    dim3 grid(CCOLS / CT, N);                // (4, 2048)
    bmm_tr_residual_kernel<<<grid, THREADS>>>(x, attn, Dm, alpha, out);
}